// round 10
// baseline (speedup 1.0000x reference)
#include <cuda_runtime.h>

// QFD2Loss: mean_b q_b A q_b^T, A[j,k] = 1 - |j-k|/(L-1), q = D - D_pred.
// Identity: q A q^T = T^2 - (2/(L-1)) * sum_t P_t*(T-P_t)
// with P_t prefix sums of q, T total (t = L-1 term is zero since P_{L-1}=T).
// O(L) per row; kernel is HBM-bound (134 MB read, 4 B written).
// Single launch: blocks accumulate into __device__ double scratch; the last
// block writes the scaled result to d_out and resets scratch (graph-safe).

#define L_DIM 64
#define ROWS_PER_BLOCK 128
#define THREADS 128
#define SMEM_PAD 65   // stride 65 floats -> bank = (row + col) mod 32, conflict-free reads

__device__ double       g_acc   = 0.0;
__device__ unsigned int g_count = 0u;

__global__ __launch_bounds__(THREADS)
void qfd2_main_kernel(const float* __restrict__ D,
                      const float* __restrict__ Dp,
                      float* __restrict__ out,
                      int B)
{
    __shared__ float q[ROWS_PER_BLOCK * SMEM_PAD];

    const int tid = threadIdx.x;
    const long long base = (long long)blockIdx.x * (ROWS_PER_BLOCK * L_DIM);

    // ---- Coalesced cooperative streaming load: 128 rows x 64 floats ----
    // float4s per block: 128*64/4 = 2048; 16 per thread. Data has zero reuse,
    // so use evict-first (.cs) loads to keep L2 clean.
    const float4* __restrict__ D4 = reinterpret_cast<const float4*>(D + base);
    const float4* __restrict__ P4 = reinterpret_cast<const float4*>(Dp + base);

    #pragma unroll
    for (int k = 0; k < (ROWS_PER_BLOCK * L_DIM / 4) / THREADS; k++) {
        const int g = tid + k * THREADS;      // float4 index within the tile
        const float4 a = __ldcs(&D4[g]);
        const float4 b = __ldcs(&P4[g]);
        const int e   = g << 2;               // element index
        const int row = e >> 6;               // / 64
        const int col = e & 63;
        float* s = &q[row * SMEM_PAD + col];
        s[0] = a.x - b.x;
        s[1] = a.y - b.y;
        s[2] = a.z - b.z;
        s[3] = a.w - b.w;
    }
    __syncthreads();

    // ---- Per-row O(L) computation (one row per thread) ----
    const float* __restrict__ r = &q[tid * SMEM_PAD];

    float T = 0.0f;
    #pragma unroll
    for (int c = 0; c < L_DIM; c++) T += r[c];

    float P = 0.0f, acc = 0.0f;
    #pragma unroll
    for (int c = 0; c < L_DIM; c++) {      // t = L-1 term is exactly zero
        P += r[c];
        acc = fmaf(P, T - P, acc);
    }

    float per = fmaf(T, T, -(2.0f / 63.0f) * acc);

    // ---- Block reduction ----
    __shared__ float red[THREADS / 32];
    #pragma unroll
    for (int o = 16; o > 0; o >>= 1)
        per += __shfl_down_sync(0xffffffffu, per, o);
    if ((tid & 31) == 0) red[tid >> 5] = per;
    __syncthreads();

    if (tid == 0) {
        float v = red[0] + red[1] + red[2] + red[3];
        atomicAdd(&g_acc, (double)v);
        __threadfence();
        unsigned int ticket = atomicAdd(&g_count, 1u);
        if (ticket == gridDim.x - 1u) {
            // Last block: publish result, reset scratch for next graph replay.
            out[0] = (float)(g_acc * (1.0 / (double)B));
            g_acc   = 0.0;
            __threadfence();
            g_count = 0u;
        }
    }
}

extern "C" void kernel_launch(void* const* d_in, const int* in_sizes, int n_in,
                              void* d_out, int out_size)
{
    const float* D  = (const float*)d_in[0];
    const float* Dp = (const float*)d_in[1];
    float* out = (float*)d_out;

    const int total = in_sizes[0];        // B * L
    const int B = total / L_DIM;          // 262144
    const int grid = B / ROWS_PER_BLOCK;  // 2048

    qfd2_main_kernel<<<grid, THREADS>>>(D, Dp, out, B);
}

// round 11
// speedup vs baseline: 1.0966x; 1.0966x over previous
#include <cuda_runtime.h>
#include <cstdint>

// QFD2Loss: mean_b q A q^T, A[j,k] = 1 - |j-k|/63, q = D - D_pred.
// Single-pass identity per row: with running prefix P, U = sum_t P_t,
// S2 = sum_t P_t^2, T = P_final:
//   q A q^T = T^2 - (2/63) * (T*U - S2)
// HBM-bound (134 MB read). cp.async double-buffered pipeline: each CTA
// streams tiles gmem->smem asynchronously while computing the previous
// tile, keeping ~32KB per CTA in flight continuously (no load/compute
// phase serialization). Grid = 148*3 CTAs at 68KB smem = exactly 3/SM,
// one wave, no quantization tail.

#define L_DIM 64
#define TILE_ROWS 64
#define THREADS 64
#define NTILES 4096          // 262144 / 64
#define GRID 444             // 148 SMs * 3 CTAs
#define ROW_STRIDE_B 272     // 68 floats: 16B-aligned pad, 4-way LDS conflict (hidden)
#define ARR_B (TILE_ROWS * ROW_STRIDE_B)   // 17408 bytes per array
#define BUF_B (2 * ARR_B)                  // 34816: D tile + Dp tile
#define SMEM_B (2 * BUF_B)                 // 69632: double buffer

__device__ double       g_acc   = 0.0;
__device__ unsigned int g_count = 0u;

__device__ __forceinline__ void cp_async16(uint32_t dst, const void* src) {
    asm volatile("cp.async.cg.shared.global [%0], [%1], 16;" :: "r"(dst), "l"(src));
}

__global__ __launch_bounds__(THREADS)
void qfd2_kernel(const float* __restrict__ D,
                 const float* __restrict__ Dp,
                 float* __restrict__ out,
                 int B)
{
    extern __shared__ char smem[];
    const uint32_t sbase = (uint32_t)__cvta_generic_to_shared(smem);
    const int tid = threadIdx.x;

    // Issue one tile (64 rows x 64 floats of D and Dp) into buffer `buf`.
    auto issue_tile = [&](int tile, int buf) {
        const char* dsrc = (const char*)D  + (size_t)tile * (TILE_ROWS * L_DIM * 4);
        const char* psrc = (const char*)Dp + (size_t)tile * (TILE_ROWS * L_DIM * 4);
        const uint32_t dbase = sbase + buf * BUF_B;
        #pragma unroll
        for (int k = 0; k < (TILE_ROWS * L_DIM * 4 / 16) / THREADS; k++) {
            const int j = tid + k * THREADS;          // 16B-chunk index, 0..1023
            const int row = j >> 4;
            const int ch  = j & 15;
            const uint32_t off = row * ROW_STRIDE_B + ch * 16;
            cp_async16(dbase + off,         dsrc + (size_t)j * 16);
            cp_async16(dbase + ARR_B + off, psrc + (size_t)j * 16);
        }
        asm volatile("cp.async.commit_group;" ::: "memory");
    };

    float thread_acc = 0.0f;
    int tile = blockIdx.x;
    int buf = 0;

    issue_tile(tile, 0);

    while (true) {
        const int next = tile + GRID;
        if (next < NTILES) {
            issue_tile(next, buf ^ 1);                   // keep pipe full
            asm volatile("cp.async.wait_group 1;" ::: "memory");  // oldest done
        } else {
            asm volatile("cp.async.wait_group 0;" ::: "memory");
        }
        __syncthreads();   // all threads' chunks visible

        // ---- one row per thread, single pass ----
        const float* __restrict__ drow =
            (const float*)(smem + buf * BUF_B + tid * ROW_STRIDE_B);
        const float* __restrict__ prow =
            (const float*)(smem + buf * BUF_B + ARR_B + tid * ROW_STRIDE_B);

        float P = 0.0f, U = 0.0f, S2 = 0.0f;
        #pragma unroll
        for (int c = 0; c < L_DIM; c++) {
            const float q = drow[c] - prow[c];
            P += q;                     // prefix sum
            U += P;                     // sum of prefixes
            S2 = fmaf(P, P, S2);        // sum of squared prefixes
        }
        const float T = P;
        // q A q^T = T^2 - (2/63)*(T*U - S2)
        thread_acc += fmaf(T, T, -(2.0f / 63.0f) * fmaf(T, U, -S2));

        __syncthreads();   // everyone done reading buf before it is refilled
        buf ^= 1;
        tile = next;
        if (tile >= NTILES) break;
    }

    // ---- block reduction (2 warps) ----
    #pragma unroll
    for (int o = 16; o > 0; o >>= 1)
        thread_acc += __shfl_down_sync(0xffffffffu, thread_acc, o);

    __shared__ float wsum[2];
    if ((tid & 31) == 0) wsum[tid >> 5] = thread_acc;
    __syncthreads();

    if (tid == 0) {
        atomicAdd(&g_acc, (double)(wsum[0] + wsum[1]));
        __threadfence();
        const unsigned int ticket = atomicAdd(&g_count, 1u);
        if (ticket == gridDim.x - 1u) {
            out[0] = (float)(g_acc * (1.0 / (double)B));
            g_acc   = 0.0;
            __threadfence();
            g_count = 0u;
        }
    }
}

extern "C" void kernel_launch(void* const* d_in, const int* in_sizes, int n_in,
                              void* d_out, int out_size)
{
    const float* D  = (const float*)d_in[0];
    const float* Dp = (const float*)d_in[1];
    float* out = (float*)d_out;

    const int B = in_sizes[0] / L_DIM;    // 262144

    cudaFuncSetAttribute(qfd2_kernel,
                         cudaFuncAttributeMaxDynamicSharedMemorySize, SMEM_B);
    qfd2_kernel<<<GRID, THREADS, SMEM_B>>>(D, Dp, out, B);
}

// round 14
// speedup vs baseline: 1.1380x; 1.0377x over previous
#include <cuda_runtime.h>
#include <cstdint>

// QFD2Loss: mean_b q A q^T, A[j,k] = 1 - |j-k|/63, q = D - D_pred.
// Per-row single pass: prefix P, U = sum P_t, S2 = sum P_t^2, T = P_final:
//   q A q^T = T^2 - (2/63) * (T*U - S2)
// HBM-bound (134 MB read). 3-deep cp.async pipeline: while computing tile j,
// tiles j+1 and j+2 (64 KB/CTA) are ALWAYS in flight -> no outstanding-bytes
// sawtooth. Empty commit_groups in the tail keep wait_group 2 constant-valid.
// Grid = 152 SMs x 2 CTAs; ~13.5 tiles per CTA work loop.

#define L_DIM 64
#define TILE_ROWS 64
#define THREADS 64
#define NTILES 4096            // 262144 / 64
#define GRID 304               // 152 SMs * 2 CTAs
#define PIPE 3
#define ROW_STRIDE_B 272       // 68 floats; float4 reads are bank-conflict-free
#define ARR_B (TILE_ROWS * ROW_STRIDE_B)   // 17408 B per array
#define BUF_B (2 * ARR_B)                  // 34816 B: D tile + Dp tile
#define SMEM_B (PIPE * BUF_B)              // 104448 B, 2 CTAs/SM = 204 KB

__device__ double       g_acc   = 0.0;
__device__ unsigned int g_count = 0u;

__device__ __forceinline__ void cp_async16(uint32_t dst, const void* src) {
    asm volatile("cp.async.cg.shared.global [%0], [%1], 16;" :: "r"(dst), "l"(src));
}

__global__ __launch_bounds__(THREADS)
void qfd2_kernel(const float* __restrict__ D,
                 const float* __restrict__ Dp,
                 float* __restrict__ out,
                 int B)
{
    extern __shared__ char smem[];
    const uint32_t sbase = (uint32_t)__cvta_generic_to_shared(smem);
    const int tid = threadIdx.x;

    // Issue one tile (64 rows x 64 floats of D and Dp) into buffer `buf`,
    // then commit. If tile is out of range, commit an EMPTY group so the
    // outstanding-group count stays in lockstep with the loop.
    auto issue_tile = [&](int tile, int buf) {
        if (tile < NTILES) {
            const char* dsrc = (const char*)D  + (size_t)tile * (TILE_ROWS * L_DIM * 4);
            const char* psrc = (const char*)Dp + (size_t)tile * (TILE_ROWS * L_DIM * 4);
            const uint32_t dbase = sbase + buf * BUF_B;
            #pragma unroll
            for (int k = 0; k < (TILE_ROWS * L_DIM * 4 / 16) / THREADS; k++) {
                const int j = tid + k * THREADS;      // 16B-chunk index, 0..1023
                const int row = j >> 4;
                const int ch  = j & 15;
                const uint32_t off = row * ROW_STRIDE_B + ch * 16;
                cp_async16(dbase + off,         dsrc + (size_t)j * 16);
                cp_async16(dbase + ARR_B + off, psrc + (size_t)j * 16);
            }
        }
        asm volatile("cp.async.commit_group;" ::: "memory");
    };

    // ---- Prologue: fill all PIPE stages ----
    #pragma unroll
    for (int p = 0; p < PIPE; p++)
        issue_tile(blockIdx.x + p * GRID, p);

    float thread_acc = 0.0f;

    for (int tile = blockIdx.x, it = 0; tile < NTILES; tile += GRID, it++) {
        const int buf = it % PIPE;

        // Oldest group (this tile) must be complete; PIPE-1 = 2 stay in flight.
        asm volatile("cp.async.wait_group %0;" :: "n"(PIPE - 1) : "memory");
        __syncthreads();

        // ---- one row per thread, float4 smem reads (conflict-free) ----
        const float4* __restrict__ drow =
            (const float4*)(smem + buf * BUF_B + tid * ROW_STRIDE_B);
        const float4* __restrict__ prow =
            (const float4*)(smem + buf * BUF_B + ARR_B + tid * ROW_STRIDE_B);

        float P = 0.0f, U = 0.0f, S2 = 0.0f;
        #pragma unroll
        for (int c = 0; c < L_DIM / 4; c++) {
            const float4 a = drow[c];
            const float4 b = prow[c];
            P += a.x - b.x;  U += P;  S2 = fmaf(P, P, S2);
            P += a.y - b.y;  U += P;  S2 = fmaf(P, P, S2);
            P += a.z - b.z;  U += P;  S2 = fmaf(P, P, S2);
            P += a.w - b.w;  U += P;  S2 = fmaf(P, P, S2);
        }
        const float T = P;
        thread_acc += fmaf(T, T, -(2.0f / 63.0f) * fmaf(T, U, -S2));

        __syncthreads();                       // all readers done with buf
        issue_tile(tile + PIPE * GRID, buf);   // refill just-freed stage
    }

    // ---- block reduction (2 warps) ----
    #pragma unroll
    for (int o = 16; o > 0; o >>= 1)
        thread_acc += __shfl_down_sync(0xffffffffu, thread_acc, o);

    __shared__ float wsum[2];
    if ((tid & 31) == 0) wsum[tid >> 5] = thread_acc;
    __syncthreads();

    if (tid == 0) {
        atomicAdd(&g_acc, (double)(wsum[0] + wsum[1]));
        __threadfence();
        const unsigned int ticket = atomicAdd(&g_count, 1u);
        if (ticket == gridDim.x - 1u) {
            out[0] = (float)(g_acc * (1.0 / (double)B));
            g_acc   = 0.0;
            __threadfence();
            g_count = 0u;
        }
    }
}

extern "C" void kernel_launch(void* const* d_in, const int* in_sizes, int n_in,
                              void* d_out, int out_size)
{
    const float* D  = (const float*)d_in[0];
    const float* Dp = (const float*)d_in[1];
    float* out = (float*)d_out;

    const int B = in_sizes[0] / L_DIM;    // 262144

    cudaFuncSetAttribute(qfd2_kernel,
                         cudaFuncAttributeMaxDynamicSharedMemorySize, SMEM_B);
    qfd2_kernel<<<GRID, THREADS, SMEM_B>>>(D, Dp, out, B);
}